// round 1
// baseline (speedup 1.0000x reference)
#include <cuda_runtime.h>

// ---------------------------------------------------------------------------
// MetricPredictor: 2-layer GCN (degree features) + sum-pool + 2-layer MLP
// N=10000 nodes, E=320000 edges (sizes read from in_sizes / device scalar).
//
// Inputs (metadata order):
//  0: W1  [2,128]   1: b1 [128]   2: W2 [128,256]  3: b2 [256]
//  4: Wp1 [256,128] 5: bp1 [128]  6: Wp2 [128,1]   7: bp2 [1]
//  8: src [E] int32 9: dst [E] int32  10: num_nodes (int32 scalar, maybe)
// Output: 257 floats = graph_embedding[256] ++ metric[1]
// ---------------------------------------------------------------------------

#define MAXN 16384
#define NTHREADS 256

// Scratch (static device globals; no allocation anywhere)
__device__ __align__(16) float g_x[2 * MAXN];       // [in_deg, out_deg] per node
__device__ __align__(16) float g_agg1[2 * MAXN];
__device__ __align__(16) float g_h1[MAXN * 128];
__device__ __align__(16) float g_agg2[MAXN * 128];
__device__ __align__(16) float g_ge[256];

__device__ __forceinline__ int get_N(const int* np) {
    return np ? __ldg(np) : 10000;
}

// ---------------------------------------------------------------------------
__global__ void k_zero() {
    int i = blockIdx.x * blockDim.x + threadIdx.x;
    int stride = gridDim.x * blockDim.x;
    for (int j = i; j < 2 * MAXN; j += stride) { g_x[j] = 0.f; g_agg1[j] = 0.f; }
    for (int j = i; j < MAXN * 128; j += stride) g_agg2[j] = 0.f;
    if (i < 256) g_ge[i] = 0.f;
}

// degrees: x[n] = [in_deg(n), out_deg(n)]
__global__ void k_deg(const int* __restrict__ src, const int* __restrict__ dst, int E) {
    int e = blockIdx.x * blockDim.x + threadIdx.x;
    if (e >= E) return;
    atomicAdd(&g_x[2 * dst[e] + 0], 1.0f);
    atomicAdd(&g_x[2 * src[e] + 1], 1.0f);
}

// agg1 = segment_sum(x[src], dst)
__global__ void k_agg1(const int* __restrict__ src, const int* __restrict__ dst, int E) {
    int e = blockIdx.x * blockDim.x + threadIdx.x;
    if (e >= E) return;
    int s = src[e], d = dst[e];
    float2 v = *(const float2*)&g_x[2 * s];
    atomicAdd(&g_agg1[2 * d + 0], v.x);
    atomicAdd(&g_agg1[2 * d + 1], v.y);
}

// h1 = relu(agg1 @ W1 + b1), W1:[2,128] row-major
__global__ void k_h1(const float* __restrict__ W1, const float* __restrict__ b1,
                     const int* __restrict__ np) {
    int N = get_N(np);
    int id = blockIdx.x * blockDim.x + threadIdx.x;
    if (id >= N * 128) return;
    int n = id >> 7, j = id & 127;
    float a0 = g_agg1[2 * n], a1 = g_agg1[2 * n + 1];
    float v = fmaf(a0, __ldg(&W1[j]), fmaf(a1, __ldg(&W1[128 + j]), __ldg(&b1[j])));
    g_h1[id] = fmaxf(v, 0.0f);
}

// agg2 = segment_sum(h1[src], dst); one warp per edge, float4 chunks, RED atomics
__global__ void k_agg2(const int* __restrict__ src, const int* __restrict__ dst, int E) {
    int t = blockIdx.x * blockDim.x + threadIdx.x;
    int e = t >> 5;
    if (e >= E) return;
    int c = t & 31;
    int s = src[e], d = dst[e];
    float4 v = *(const float4*)&g_h1[s * 128 + c * 4];
    float* p = &g_agg2[d * 128 + c * 4];
    atomicAdd(p + 0, v.x);
    atomicAdd(p + 1, v.y);
    atomicAdd(p + 2, v.z);
    atomicAdd(p + 3, v.w);
}

// h2 = relu(agg2 @ W2 + b2); graph_embedding += sum over the block's 32 nodes.
// Block tile: 32 nodes x 256 cols; thread tile: 8 nodes x 4 cols.
__global__ void __launch_bounds__(256) k_h2sum(const float* __restrict__ W2,
                                               const float* __restrict__ b2,
                                               const int* __restrict__ np) {
    int N = get_N(np);
    int base = blockIdx.x * 32;
    if (base >= N) return;

    __shared__ float s_a[32 * 128];   // agg2 tile
    __shared__ float s_ge[256];

    int t = threadIdx.x;
    s_ge[t] = 0.0f;

    // load agg2 tile (zero-padded past N): 1024 float4s, 4 per thread
    for (int i = t; i < 32 * 128 / 4; i += 256) {
        int n = base + (i >> 5);
        float4 v = make_float4(0.f, 0.f, 0.f, 0.f);
        if (n < N) v = *(const float4*)&g_agg2[n * 128 + (i & 31) * 4];
        *(float4*)&s_a[i * 4] = v;
    }
    __syncthreads();

    int jg = t & 63;   // column group (4 cols each)
    int mg = t >> 6;   // node group (8 nodes each)

    float acc[8][4];
#pragma unroll
    for (int m = 0; m < 8; m++)
#pragma unroll
        for (int c = 0; c < 4; c++) acc[m][c] = 0.0f;

    const float* sa = &s_a[mg * 8 * 128];
    for (int k = 0; k < 128; k++) {
        float4 w = *(const float4*)&W2[k * 256 + jg * 4];
#pragma unroll
        for (int m = 0; m < 8; m++) {
            float a = sa[m * 128 + k];
            acc[m][0] = fmaf(a, w.x, acc[m][0]);
            acc[m][1] = fmaf(a, w.y, acc[m][1]);
            acc[m][2] = fmaf(a, w.z, acc[m][2]);
            acc[m][3] = fmaf(a, w.w, acc[m][3]);
        }
    }

    float4 bb = *(const float4*)&b2[jg * 4];
    float p0 = 0.f, p1 = 0.f, p2 = 0.f, p3 = 0.f;
#pragma unroll
    for (int m = 0; m < 8; m++) {
        if (base + mg * 8 + m < N) {
            p0 += fmaxf(acc[m][0] + bb.x, 0.0f);
            p1 += fmaxf(acc[m][1] + bb.y, 0.0f);
            p2 += fmaxf(acc[m][2] + bb.z, 0.0f);
            p3 += fmaxf(acc[m][3] + bb.w, 0.0f);
        }
    }
    atomicAdd(&s_ge[jg * 4 + 0], p0);
    atomicAdd(&s_ge[jg * 4 + 1], p1);
    atomicAdd(&s_ge[jg * 4 + 2], p2);
    atomicAdd(&s_ge[jg * 4 + 3], p3);
    __syncthreads();
    atomicAdd(&g_ge[t], s_ge[t]);
}

// final MLP + output write
__global__ void k_final(const float* __restrict__ Wp1, const float* __restrict__ bp1,
                        const float* __restrict__ Wp2, const float* __restrict__ bp2,
                        float* __restrict__ out) {
    __shared__ float s_ge[256];
    __shared__ float s_m[128];
    int t = threadIdx.x;   // 256 threads
    float ge = g_ge[t];
    s_ge[t] = ge;
    out[t] = ge;
    __syncthreads();
    if (t < 128) {
        float acc = bp1[t];
        for (int k = 0; k < 256; k++)
            acc = fmaf(s_ge[k], __ldg(&Wp1[k * 128 + t]), acc);
        s_m[t] = fmaxf(acc, 0.0f) * __ldg(&Wp2[t]);
    }
    __syncthreads();
    for (int off = 64; off >= 1; off >>= 1) {
        if (t < off) s_m[t] += s_m[t + off];
        __syncthreads();
    }
    if (t == 0) out[256] = s_m[0] + bp2[0];
}

// ---------------------------------------------------------------------------
extern "C" void kernel_launch(void* const* d_in, const int* in_sizes, int n_in,
                              void* d_out, int out_size) {
    const float* W1  = (const float*)d_in[0];
    const float* b1  = (const float*)d_in[1];
    const float* W2  = (const float*)d_in[2];
    const float* b2  = (const float*)d_in[3];
    const float* Wp1 = (const float*)d_in[4];
    const float* bp1 = (const float*)d_in[5];
    const float* Wp2 = (const float*)d_in[6];
    const float* bp2 = (const float*)d_in[7];
    const int*   src = (const int*)d_in[8];
    const int*   dst = (const int*)d_in[9];
    const int*   np  = (n_in > 10) ? (const int*)d_in[10] : nullptr;
    int E = in_sizes[8];

    k_zero<<<2048, NTHREADS>>>();
    k_deg<<<(E + NTHREADS - 1) / NTHREADS, NTHREADS>>>(src, dst, E);
    k_agg1<<<(E + NTHREADS - 1) / NTHREADS, NTHREADS>>>(src, dst, E);
    k_h1<<<(MAXN * 128) / NTHREADS, NTHREADS>>>(W1, b1, np);
    {
        long long tot = (long long)E * 32;
        int blocks = (int)((tot + NTHREADS - 1) / NTHREADS);
        k_agg2<<<blocks, NTHREADS>>>(src, dst, E);
    }
    k_h2sum<<<MAXN / 32, NTHREADS>>>(W2, b2, np);
    k_final<<<1, NTHREADS>>>(Wp1, bp1, Wp2, bp2, (float*)d_out);
    (void)out_size; (void)n_in;
}

// round 2
// speedup vs baseline: 1.7329x; 1.7329x over previous
#include <cuda_runtime.h>

// ---------------------------------------------------------------------------
// MetricPredictor: 2-layer GCN (degree features) + sum-pool + 2-layer MLP
// CSR-gather formulation (no float atomics on the wide aggregation).
//
// Inputs (metadata order):
//  0: W1  [2,128]   1: b1 [128]   2: W2 [128,256]  3: b2 [256]
//  4: Wp1 [256,128] 5: bp1 [128]  6: Wp2 [128,1]   7: bp2 [1]
//  8: src [E] int32 9: dst [E] int32  10: num_nodes (int32 scalar)
// Output: 257 floats = graph_embedding[256] ++ metric[1]
// ---------------------------------------------------------------------------

#define MAXN 16384
#define MAXE 524288
#define NTHREADS 256
#define FULLMASK 0xFFFFFFFFu

// Scratch (static device globals; no allocation anywhere)
__device__ __align__(16) int   g_incnt[MAXN];
__device__ __align__(16) int   g_outcnt[MAXN];
__device__ __align__(16) int   g_rowoff[MAXN + 1];
__device__ __align__(16) int   g_cursor[MAXN];
__device__ __align__(16) int   g_csrc[MAXE];        // CSR-by-dst: source ids
__device__ __align__(16) float g_h1[MAXN * 128];
__device__ __align__(16) float g_agg2[MAXN * 128];
__device__ __align__(16) float g_ge[256];

__device__ __forceinline__ int get_N(const int* np) {
    return np ? __ldg(np) : 10000;
}

// ---------------------------------------------------------------------------
__global__ void k_zero() {
    int i = blockIdx.x * blockDim.x + threadIdx.x;
    int stride = gridDim.x * blockDim.x;
    for (int j = i; j < MAXN; j += stride) { g_incnt[j] = 0; g_outcnt[j] = 0; }
    if (i < 256) g_ge[i] = 0.f;
}

// degree counts (int atomics)
__global__ void k_count(const int* __restrict__ src, const int* __restrict__ dst, int E) {
    int e = blockIdx.x * blockDim.x + threadIdx.x;
    if (e >= E) return;
    atomicAdd(&g_incnt[dst[e]], 1);
    atomicAdd(&g_outcnt[src[e]], 1);
}

// exclusive scan of g_incnt over MAXN -> g_rowoff, g_cursor (single block, 1024 thr)
__global__ void __launch_bounds__(1024) k_scan() {
    __shared__ int s_part[1024];
    const int CH = MAXN / 1024;  // 16
    int t = threadIdx.x;
    int base = t * CH;
    int loc[CH];
    int sum = 0;
#pragma unroll
    for (int i = 0; i < CH; i++) { loc[i] = sum; sum += g_incnt[base + i]; }
    s_part[t] = sum;
    __syncthreads();
    for (int off = 1; off < 1024; off <<= 1) {
        int v = (t >= off) ? s_part[t - off] : 0;
        __syncthreads();
        s_part[t] += v;
        __syncthreads();
    }
    int pre = (t > 0) ? s_part[t - 1] : 0;
#pragma unroll
    for (int i = 0; i < CH; i++) {
        int o = pre + loc[i];
        g_rowoff[base + i] = o;
        g_cursor[base + i] = o;
    }
    if (t == 1023) g_rowoff[MAXN] = s_part[1023];
}

// fill CSR: csr_src[cursor[dst]++] = src
__global__ void k_fill(const int* __restrict__ src, const int* __restrict__ dst, int E) {
    int e = blockIdx.x * blockDim.x + threadIdx.x;
    if (e >= E) return;
    int pos = atomicAdd(&g_cursor[dst[e]], 1);
    g_csrc[pos] = src[e];
}

// fused: agg1 = segment_sum(x[src], dst) with x = [in_deg, out_deg], then
// h1 = relu(agg1 @ W1 + b1). One warp per node.
__global__ void k_l1(const float* __restrict__ W1, const float* __restrict__ b1,
                     const int* __restrict__ np) {
    int N = get_N(np);
    int w = (blockIdx.x * blockDim.x + threadIdx.x) >> 5;
    if (w >= N) return;
    int lane = threadIdx.x & 31;
    int beg = g_rowoff[w];
    int end = beg + g_incnt[w];
    float a0 = 0.f, a1 = 0.f;
    for (int j = beg + lane; j < end; j += 32) {
        int s = g_csrc[j];
        a0 += (float)__ldg(&g_incnt[s]);
        a1 += (float)__ldg(&g_outcnt[s]);
    }
#pragma unroll
    for (int off = 16; off >= 1; off >>= 1) {
        a0 += __shfl_down_sync(FULLMASK, a0, off);
        a1 += __shfl_down_sync(FULLMASK, a1, off);
    }
    a0 = __shfl_sync(FULLMASK, a0, 0);
    a1 = __shfl_sync(FULLMASK, a1, 0);
    float4 r;
    int j = lane * 4;
    r.x = fmaxf(fmaf(a0, __ldg(&W1[j + 0]), fmaf(a1, __ldg(&W1[128 + j + 0]), __ldg(&b1[j + 0]))), 0.f);
    r.y = fmaxf(fmaf(a0, __ldg(&W1[j + 1]), fmaf(a1, __ldg(&W1[128 + j + 1]), __ldg(&b1[j + 1]))), 0.f);
    r.z = fmaxf(fmaf(a0, __ldg(&W1[j + 2]), fmaf(a1, __ldg(&W1[128 + j + 2]), __ldg(&b1[j + 2]))), 0.f);
    r.w = fmaxf(fmaf(a0, __ldg(&W1[j + 3]), fmaf(a1, __ldg(&W1[128 + j + 3]), __ldg(&b1[j + 3]))), 0.f);
    *(float4*)&g_h1[w * 128 + j] = r;
}

// agg2 = segment_sum(h1[src], dst); one warp per node, gather-reduce, no atomics
__global__ void k_agg2(const int* __restrict__ np) {
    int N = get_N(np);
    int w = (blockIdx.x * blockDim.x + threadIdx.x) >> 5;
    if (w >= N) return;
    int lane = threadIdx.x & 31;
    int beg = g_rowoff[w];
    int end = beg + g_incnt[w];
    float4 acc = make_float4(0.f, 0.f, 0.f, 0.f);
    for (int j0 = beg; j0 < end; j0 += 32) {
        int m = end - j0; if (m > 32) m = 32;
        int sl = (lane < m) ? g_csrc[j0 + lane] : 0;
        for (int k = 0; k < m; k++) {
            int s = __shfl_sync(FULLMASK, sl, k);
            float4 v = *(const float4*)&g_h1[s * 128 + lane * 4];
            acc.x += v.x; acc.y += v.y; acc.z += v.z; acc.w += v.w;
        }
    }
    *(float4*)&g_agg2[w * 128 + lane * 4] = acc;
}

// h2 = relu(agg2 @ W2 + b2); graph_embedding += sum over the block's 32 nodes.
__global__ void __launch_bounds__(256) k_h2sum(const float* __restrict__ W2,
                                               const float* __restrict__ b2,
                                               const int* __restrict__ np) {
    int N = get_N(np);
    int base = blockIdx.x * 32;
    if (base >= N) return;

    __shared__ float s_a[32 * 128];
    __shared__ float s_ge[256];

    int t = threadIdx.x;
    s_ge[t] = 0.0f;

    for (int i = t; i < 32 * 128 / 4; i += 256) {
        int n = base + (i >> 5);
        float4 v = make_float4(0.f, 0.f, 0.f, 0.f);
        if (n < N) v = *(const float4*)&g_agg2[n * 128 + (i & 31) * 4];
        *(float4*)&s_a[i * 4] = v;
    }
    __syncthreads();

    int jg = t & 63;
    int mg = t >> 6;

    float acc[8][4];
#pragma unroll
    for (int m = 0; m < 8; m++)
#pragma unroll
        for (int c = 0; c < 4; c++) acc[m][c] = 0.0f;

    const float* sa = &s_a[mg * 8 * 128];
    for (int k = 0; k < 128; k++) {
        float4 wv = *(const float4*)&W2[k * 256 + jg * 4];
#pragma unroll
        for (int m = 0; m < 8; m++) {
            float a = sa[m * 128 + k];
            acc[m][0] = fmaf(a, wv.x, acc[m][0]);
            acc[m][1] = fmaf(a, wv.y, acc[m][1]);
            acc[m][2] = fmaf(a, wv.z, acc[m][2]);
            acc[m][3] = fmaf(a, wv.w, acc[m][3]);
        }
    }

    float4 bb = *(const float4*)&b2[jg * 4];
    float p0 = 0.f, p1 = 0.f, p2 = 0.f, p3 = 0.f;
#pragma unroll
    for (int m = 0; m < 8; m++) {
        if (base + mg * 8 + m < N) {
            p0 += fmaxf(acc[m][0] + bb.x, 0.0f);
            p1 += fmaxf(acc[m][1] + bb.y, 0.0f);
            p2 += fmaxf(acc[m][2] + bb.z, 0.0f);
            p3 += fmaxf(acc[m][3] + bb.w, 0.0f);
        }
    }
    atomicAdd(&s_ge[jg * 4 + 0], p0);
    atomicAdd(&s_ge[jg * 4 + 1], p1);
    atomicAdd(&s_ge[jg * 4 + 2], p2);
    atomicAdd(&s_ge[jg * 4 + 3], p3);
    __syncthreads();
    atomicAdd(&g_ge[t], s_ge[t]);
}

// final MLP + output write
__global__ void k_final(const float* __restrict__ Wp1, const float* __restrict__ bp1,
                        const float* __restrict__ Wp2, const float* __restrict__ bp2,
                        float* __restrict__ out) {
    __shared__ float s_ge[256];
    __shared__ float s_m[128];
    int t = threadIdx.x;   // 256 threads
    float ge = g_ge[t];
    s_ge[t] = ge;
    out[t] = ge;
    __syncthreads();
    if (t < 128) {
        float acc = bp1[t];
        for (int k = 0; k < 256; k++)
            acc = fmaf(s_ge[k], __ldg(&Wp1[k * 128 + t]), acc);
        s_m[t] = fmaxf(acc, 0.0f) * __ldg(&Wp2[t]);
    }
    __syncthreads();
    for (int off = 64; off >= 1; off >>= 1) {
        if (t < off) s_m[t] += s_m[t + off];
        __syncthreads();
    }
    if (t == 0) out[256] = s_m[0] + bp2[0];
}

// ---------------------------------------------------------------------------
extern "C" void kernel_launch(void* const* d_in, const int* in_sizes, int n_in,
                              void* d_out, int out_size) {
    const float* W1  = (const float*)d_in[0];
    const float* b1  = (const float*)d_in[1];
    const float* W2  = (const float*)d_in[2];
    const float* b2  = (const float*)d_in[3];
    const float* Wp1 = (const float*)d_in[4];
    const float* bp1 = (const float*)d_in[5];
    const float* Wp2 = (const float*)d_in[6];
    const float* bp2 = (const float*)d_in[7];
    const int*   src = (const int*)d_in[8];
    const int*   dst = (const int*)d_in[9];
    const int*   np  = (n_in > 10) ? (const int*)d_in[10] : nullptr;
    int E = in_sizes[8];

    int eb = (E + NTHREADS - 1) / NTHREADS;
    k_zero<<<64, NTHREADS>>>();
    k_count<<<eb, NTHREADS>>>(src, dst, E);
    k_scan<<<1, 1024>>>();
    k_fill<<<eb, NTHREADS>>>(src, dst, E);
    k_l1<<<(MAXN * 32 + NTHREADS - 1) / NTHREADS, NTHREADS>>>(W1, b1, np);
    k_agg2<<<(MAXN * 32 + NTHREADS - 1) / NTHREADS, NTHREADS>>>(np);
    k_h2sum<<<MAXN / 32, NTHREADS>>>(W2, b2, np);
    k_final<<<1, NTHREADS>>>(Wp1, bp1, Wp2, bp2, (float*)d_out);
    (void)out_size; (void)n_in;
}